// round 2
// baseline (speedup 1.0000x reference)
#include <cuda_runtime.h>

// ---------------------------------------------------------------------------
// Fused LSTMMeasurementPredictor — round 2
//   B=131072, H=128, NQ=2, P=32, D_IN=17, T=16
// One time loop per 64-batch tile, all state in SMEM.
// New: fma.rn.f32x2 (FFMA2) packed math + 512 threads/CTA + duplicated-pair
// weight layout so the inner loop has no pack/mov overhead.
// ---------------------------------------------------------------------------

#define NTH 512
#define BT  64
#define SS_ 68   // padded row stride (floats) for [K][64] smem buffers

// smem layout offsets (floats)
constexpr int OFF_X   = 0;                  // 17  rows : x (17-dim input)
constexpr int OFF_HC  = OFF_X  + 17 * SS_;  // 128 rows : cell h
constexpr int OFF_CC  = OFF_HC + 128 * SS_; // 128 rows : cell c
constexpr int OFF_H0  = OFF_CC + 128 * SS_; // 32  rows : lstm0 proj h
constexpr int OFF_C0  = OFF_H0 + 32 * SS_;  // 128 rows : lstm0 c
constexpr int OFF_H1  = OFF_C0 + 128 * SS_; // 32  rows : lstm1 proj h
constexpr int OFF_C1  = OFF_H1 + 32 * SS_;  // 128 rows : lstm1 c
constexpr int OFF_S   = OFF_C1 + 128 * SS_; // 128 rows : s / h_new staging
constexpr int OFF_RHO = OFF_S  + 128 * SS_; // 64*33    : rho (b-major, pad 33)
constexpr int OFF_V   = OFF_RHO + 64 * 33;  // 8 rows   : projector v
constexpr int SMEM_FLOATS = OFF_V + 8 * SS_;
constexpr int SMEM_BYTES  = SMEM_FLOATS * 4;  // ~207 KB

// packed weights. Gate-interleaved columns jp = u*4 + gate (gate order i,f,g,o)
// DUPLICATED-PAIR layout: Wd[(k*512 + jp)*2 + {0,1}] both = W[k][jp]
// so one LDG.128 yields two columns, each already (w,w)-packed for FFMA2.
__device__ __align__(16) float g_Wc[145 * 512 * 2];   // cell: [x(17); h(128)]
__device__ __align__(16) float g_bc[512 * 2];
__device__ __align__(16) float g_W0[49 * 512 * 2];    // lstm0: [x(17); hp(32)]
__device__ __align__(16) float g_b0[512 * 2];
__device__ __align__(16) float g_W1[64 * 512 * 2];    // lstm1: [hp0(32); hp1(32)]
__device__ __align__(16) float g_b1[512 * 2];
__device__ __align__(16) float g_Whr0T[128 * 32];     // [k][n] (plain)
__device__ __align__(16) float g_Whr1T[128 * 32];
__device__ __align__(16) float g_WpT[128 * 8];

__global__ void prep_kernel(
    const float* __restrict__ Wihc, const float* __restrict__ Whhc,
    const float* __restrict__ bihc, const float* __restrict__ bhhc,
    const float* __restrict__ Wp,
    const float* __restrict__ Wih0, const float* __restrict__ Whh0,
    const float* __restrict__ bih0, const float* __restrict__ bhh0,
    const float* __restrict__ Whr0,
    const float* __restrict__ Wih1, const float* __restrict__ Whh1,
    const float* __restrict__ bih1, const float* __restrict__ bhh1,
    const float* __restrict__ Whr1)
{
    int i0 = blockIdx.x * blockDim.x + threadIdx.x;
    int stride = gridDim.x * blockDim.x;

    for (int i = i0; i < 145 * 512; i += stride) {
        int k = i >> 9, jp = i & 511;
        int u = jp >> 2, g = jp & 3, j = g * 128 + u;
        float v = (k < 17) ? Wihc[j * 17 + k] : Whhc[j * 128 + (k - 17)];
        g_Wc[i * 2] = v; g_Wc[i * 2 + 1] = v;
    }
    for (int i = i0; i < 49 * 512; i += stride) {
        int k = i >> 9, jp = i & 511;
        int u = jp >> 2, g = jp & 3, j = g * 128 + u;
        float v = (k < 17) ? Wih0[j * 17 + k] : Whh0[j * 32 + (k - 17)];
        g_W0[i * 2] = v; g_W0[i * 2 + 1] = v;
    }
    for (int i = i0; i < 64 * 512; i += stride) {
        int k = i >> 9, jp = i & 511;
        int u = jp >> 2, g = jp & 3, j = g * 128 + u;
        float v = (k < 32) ? Wih1[j * 32 + k] : Whh1[j * 32 + (k - 32)];
        g_W1[i * 2] = v; g_W1[i * 2 + 1] = v;
    }
    for (int i = i0; i < 512; i += stride) {
        int u = i >> 2, g = i & 3, j = g * 128 + u;
        float vc = bihc[j] + bhhc[j];
        float v0 = bih0[j] + bhh0[j];
        float v1 = bih1[j] + bhh1[j];
        g_bc[i * 2] = vc; g_bc[i * 2 + 1] = vc;
        g_b0[i * 2] = v0; g_b0[i * 2 + 1] = v0;
        g_b1[i * 2] = v1; g_b1[i * 2 + 1] = v1;
    }
    for (int i = i0; i < 128 * 32; i += stride) {
        int k = i >> 5, n = i & 31;
        g_Whr0T[i] = Whr0[n * 128 + k];
        g_Whr1T[i] = Whr1[n * 128 + k];
    }
    for (int i = i0; i < 128 * 8; i += stride) {
        int k = i >> 3, n = i & 7;
        g_WpT[i] = Wp[n * 128 + k];
    }
}

// ---------------------------------------------------------------------------
typedef unsigned long long ull;

__device__ __forceinline__ void fma2(ull& acc, ull a, ull b) {
    asm("fma.rn.f32x2 %0, %1, %2, %0;" : "+l"(acc) : "l"(a), "l"(b));
}
__device__ __forceinline__ ull dup2(float x) {
    ull r;
    asm("mov.b64 %0, {%1, %1};" : "=l"(r) : "f"(x));
    return r;
}
__device__ __forceinline__ void unpk(ull v, float& lo, float& hi) {
    asm("mov.b64 {%0, %1}, %2;" : "=f"(lo), "=f"(hi) : "l"(v));
}

__device__ __forceinline__ float fsig(float x) {
    return __fdividef(1.0f, 1.0f + __expf(-x));
}
__device__ __forceinline__ float ftanh(float x) {
    return __fdividef(2.0f, 1.0f + __expf(-2.0f * x)) - 1.0f;
}

// One LSTM gate GEMM + elementwise update (FFMA2).
// G[64,512] = [A(KA); B(KB)] @ W + bias, gate-interleaved columns.
// Thread (n_t=tid&31, b_t=tid>>5): per cc it owns unit u=cc*32+n_t (4 gates)
// for batches b0=b_t*4 .. b0+3 (two f32x2 pairs).
template <int KA, int KB>
__device__ __forceinline__ void lstm_gemm(
    const float* __restrict__ Wd, const float* __restrict__ biasd,
    const float* shA, const float* shB, float* shC, float* shOut,
    int n_t, int b_t)
{
    const int b0 = b_t * 4;
#pragma unroll 1
    for (int cc = 0; cc < 4; ++cc) {
        const int ncol = cc * 128 + n_t * 4;     // first of 4 gate columns
        // acc[gate][pair]; init from duplicated bias
        ulonglong2 bs01 = *(const ulonglong2*)(biasd + ncol * 2);
        ulonglong2 bs23 = *(const ulonglong2*)(biasd + ncol * 2 + 4);
        ull acc[4][2];
        acc[0][0] = bs01.x; acc[0][1] = bs01.x;
        acc[1][0] = bs01.y; acc[1][1] = bs01.y;
        acc[2][0] = bs23.x; acc[2][1] = bs23.x;
        acc[3][0] = bs23.y; acc[3][1] = bs23.y;

        const float* Wa = Wd + ncol * 2;
#pragma unroll 8
        for (int k = 0; k < KA; ++k) {
            ulonglong2 w01 = __ldg((const ulonglong2*)(Wa + k * 1024));
            ulonglong2 w23 = __ldg((const ulonglong2*)(Wa + k * 1024 + 4));
            ulonglong2 a   = *(const ulonglong2*)(shA + k * SS_ + b0);
            fma2(acc[0][0], w01.x, a.x); fma2(acc[0][1], w01.x, a.y);
            fma2(acc[1][0], w01.y, a.x); fma2(acc[1][1], w01.y, a.y);
            fma2(acc[2][0], w23.x, a.x); fma2(acc[2][1], w23.x, a.y);
            fma2(acc[3][0], w23.y, a.x); fma2(acc[3][1], w23.y, a.y);
        }
        const float* Wb = Wd + (KA * 512 + ncol) * 2;
#pragma unroll 8
        for (int k = 0; k < KB; ++k) {
            ulonglong2 w01 = __ldg((const ulonglong2*)(Wb + k * 1024));
            ulonglong2 w23 = __ldg((const ulonglong2*)(Wb + k * 1024 + 4));
            ulonglong2 a   = *(const ulonglong2*)(shB + k * SS_ + b0);
            fma2(acc[0][0], w01.x, a.x); fma2(acc[0][1], w01.x, a.y);
            fma2(acc[1][0], w01.y, a.x); fma2(acc[1][1], w01.y, a.y);
            fma2(acc[2][0], w23.x, a.x); fma2(acc[2][1], w23.x, a.y);
            fma2(acc[3][0], w23.y, a.x); fma2(acc[3][1], w23.y, a.y);
        }
        // epilogue: unpack gates, c update, s = sig(o)*tanh(c_new)
        const int u = cc * 32 + n_t;
        float gi[4], gf[4], gg[4], go[4];
        unpk(acc[0][0], gi[0], gi[1]); unpk(acc[0][1], gi[2], gi[3]);
        unpk(acc[1][0], gf[0], gf[1]); unpk(acc[1][1], gf[2], gf[3]);
        unpk(acc[2][0], gg[0], gg[1]); unpk(acc[2][1], gg[2], gg[3]);
        unpk(acc[3][0], go[0], go[1]); unpk(acc[3][1], go[2], go[3]);
        float4 cv = *(const float4*)(shC + u * SS_ + b0);
        float cb[4] = {cv.x, cv.y, cv.z, cv.w};
        float sb[4];
#pragma unroll
        for (int bb = 0; bb < 4; ++bb) {
            float cn = fsig(gf[bb]) * cb[bb] + fsig(gi[bb]) * ftanh(gg[bb]);
            cb[bb] = cn;
            sb[bb] = fsig(go[bb]) * ftanh(cn);
        }
        *(float4*)(shC + u * SS_ + b0)   = make_float4(cb[0], cb[1], cb[2], cb[3]);
        *(float4*)(shOut + u * SS_ + b0) = make_float4(sb[0], sb[1], sb[2], sb[3]);
    }
}

// hp[64,32] = s[64,128] @ WhrT[128,32]; optionally also store to global out.
// 512 threads: n4 = (tid&7)*4 cols, b = tid>>3 (one batch).
__device__ __forceinline__ void proj_gemm(
    const float* __restrict__ WT, const float* shS, float* shHdst,
    float* outp, int tid)
{
    const int n4 = (tid & 7) * 4;
    const int b  = tid >> 3;
    ull acc2[2] = {0ull, 0ull};
#pragma unroll 8
    for (int k = 0; k < 128; ++k) {
        ulonglong2 wp = __ldg((const ulonglong2*)(WT + k * 32 + n4));
        ull sd = dup2(shS[k * SS_ + b]);
        fma2(acc2[0], wp.x, sd);
        fma2(acc2[1], wp.y, sd);
    }
    float a0, a1, a2, a3;
    unpk(acc2[0], a0, a1);
    unpk(acc2[1], a2, a3);
    shHdst[(n4 + 0) * SS_ + b] = a0;
    shHdst[(n4 + 1) * SS_ + b] = a1;
    shHdst[(n4 + 2) * SS_ + b] = a2;
    shHdst[(n4 + 3) * SS_ + b] = a3;
    if (outp) {
        *(float4*)(outp + (size_t)b * 512 + n4) = make_float4(a0, a1, a2, a3);
    }
}

// quantum measurement physics for one batch element b (0..63)
__device__ __forceinline__ void physics(const float* shV, const float* shRHO,
                                        float* shX, int b)
{
    float Mr[2][2][2], Mi[2][2][2];
#pragma unroll
    for (int q = 0; q < 2; ++q) {
        float ar = shV[(q * 4 + 0) * SS_ + b];
        float ai = shV[(q * 4 + 1) * SS_ + b];
        float br = shV[(q * 4 + 2) * SS_ + b];
        float bi = shV[(q * 4 + 3) * SS_ + b];
        float n00 = ar * ar + ai * ai;
        float n11 = br * br + bi * bi;
        float inv = 1.0f / (n00 + n11);
        float pr = (ar * br + ai * bi) * inv;
        float pi = (ai * br - ar * bi) * inv;
        Mr[q][0][0] = n00 * inv; Mi[q][0][0] = 0.f;
        Mr[q][0][1] = pr;        Mi[q][0][1] = pi;
        Mr[q][1][0] = pr;        Mi[q][1][0] = -pi;
        Mr[q][1][1] = n11 * inv; Mi[q][1][1] = 0.f;
    }
    const float* rp = shRHO + b * 33;
    float m = 0.f;
#pragma unroll
    for (int a = 0; a < 2; ++a)
#pragma unroll
        for (int c = 0; c < 2; ++c)
#pragma unroll
            for (int b2 = 0; b2 < 2; ++b2)
#pragma unroll
                for (int d = 0; d < 2; ++d) {
                    float tr_ = Mr[0][a][c] * Mr[1][b2][d] - Mi[0][a][c] * Mi[1][b2][d];
                    float ti_ = Mr[0][a][c] * Mi[1][b2][d] + Mi[0][a][c] * Mr[1][b2][d];
                    int row = c * 2 + d, col = a * 2 + b2;
                    float rr = rp[row * 4 + col];
                    float ri = rp[16 + row * 4 + col];
                    m += tr_ * rr - ti_ * ri;
                }
    shX[0 * SS_ + b] = m;
#pragma unroll
    for (int q = 0; q < 2; ++q)
#pragma unroll
        for (int i = 0; i < 2; ++i)
#pragma unroll
            for (int j = 0; j < 2; ++j) {
                int base = 1 + 8 * q + 4 * i + 2 * j;
                shX[base * SS_ + b]       = Mr[q][i][j];
                shX[(base + 1) * SS_ + b] = Mi[q][i][j];
            }
}

__global__ void __launch_bounds__(NTH, 1) fused_kernel(
    const float* __restrict__ meas, const float* __restrict__ basis_r,
    const float* __restrict__ basis_i, const float* __restrict__ rho,
    const float* __restrict__ h0in, const float* __restrict__ c0in,
    const float* __restrict__ bp, float* __restrict__ out)
{
    extern __shared__ float sm[];
    float* shX   = sm + OFF_X;
    float* shHC  = sm + OFF_HC;
    float* shCC  = sm + OFF_CC;
    float* shH0  = sm + OFF_H0;
    float* shC0  = sm + OFF_C0;
    float* shH1  = sm + OFF_H1;
    float* shC1  = sm + OFF_C1;
    float* shS   = sm + OFF_S;
    float* shRHO = sm + OFF_RHO;
    float* shV   = sm + OFF_V;

    const int tid = threadIdx.x;
    const int b0g = blockIdx.x * BT;

    // ---- init loads ----
    for (int i = tid; i < BT; i += NTH)
        shX[0 * SS_ + i] = meas[b0g + i];
    for (int i = tid; i < BT * 8; i += NTH) {
        int b = i >> 3, e = i & 7;
        shX[(1 + 2 * e) * SS_ + b] = basis_r[(size_t)(b0g + b) * 8 + e];
        shX[(2 + 2 * e) * SS_ + b] = basis_i[(size_t)(b0g + b) * 8 + e];
    }
    for (int i = tid; i < BT * 32; i += NTH) {
        int b = i >> 5, e = i & 31;
        shRHO[b * 33 + e] = rho[(size_t)(b0g + b) * 32 + e];
    }
    for (int i = tid; i < BT * 128; i += NTH) {
        int b = i >> 7, u = i & 127;
        shHC[u * SS_ + b] = h0in[(size_t)(b0g + b) * 128 + u];
        shCC[u * SS_ + b] = c0in[(size_t)(b0g + b) * 128 + u];
    }
    // zero h0/c0/h1/c1 (320 consecutive rows starting at OFF_H0)
    for (int i = tid; i < 320 * SS_; i += NTH)
        sm[OFF_H0 + i] = 0.f;
    __syncthreads();

    const int n_t = tid & 31;
    const int b_t = tid >> 5;

    for (int t = 0; t < 16; ++t) {
        // LSTM0 step: input [x(17); hp0(32)]
        lstm_gemm<17, 32>(g_W0, g_b0, shX, shH0, shC0, shS, n_t, b_t);
        __syncthreads();
        proj_gemm(g_Whr0T, shS, shH0, nullptr, tid);
        __syncthreads();
        // LSTM1 step: input [hp0(32); hp1(32)]
        lstm_gemm<32, 32>(g_W1, g_b1, shH0, shH1, shC1, shS, n_t, b_t);
        __syncthreads();
        proj_gemm(g_Whr1T, shS, shH1,
                  out + (size_t)b0g * 512 + (size_t)t * 32, tid);
        __syncthreads();

        if (t < 15) {
            // cell step: input [x(17); h_cell(128)]; h_new staged into shS
            lstm_gemm<17, 128>(g_Wc, g_bc, shX, shHC, shCC, shS, n_t, b_t);
            __syncthreads();
            // projector v[64,8] = h_new @ WpT + bp   (512 threads, 1 elt each)
            {
                int nn = tid >> 6, bb = tid & 63;
                float a = __ldg(&bp[nn]);
#pragma unroll 8
                for (int k = 0; k < 128; ++k)
                    a += shS[k * SS_ + bb] * __ldg(&g_WpT[k * 8 + nn]);
                shV[nn * SS_ + bb] = a;
            }
            // copy h_new (shS) -> shHC (vectorized, 16 float4 per thread)
            __syncthreads();
            if (tid < BT) physics(shV, shRHO, shX, tid);
            for (int i = tid; i < 128 * 16; i += NTH) {
                int u = i >> 4, b4 = (i & 15) * 4;
                *(float4*)(shHC + u * SS_ + b4) =
                    *(const float4*)(shS + u * SS_ + b4);
            }
            __syncthreads();
        }
    }
}

extern "C" void kernel_launch(void* const* d_in, const int* in_sizes, int n_in,
                              void* d_out, int out_size)
{
    const float* meas   = (const float*)d_in[0];
    const float* br     = (const float*)d_in[1];
    const float* bi     = (const float*)d_in[2];
    const float* rho    = (const float*)d_in[3];
    const float* h0     = (const float*)d_in[4];
    const float* c0     = (const float*)d_in[5];
    const float* Wihc   = (const float*)d_in[6];
    const float* Whhc   = (const float*)d_in[7];
    const float* bihc   = (const float*)d_in[8];
    const float* bhhc   = (const float*)d_in[9];
    const float* Wp     = (const float*)d_in[10];
    const float* bp     = (const float*)d_in[11];
    const float* Wih0   = (const float*)d_in[12];
    const float* Whh0   = (const float*)d_in[13];
    const float* bih0   = (const float*)d_in[14];
    const float* bhh0   = (const float*)d_in[15];
    const float* Whr0   = (const float*)d_in[16];
    const float* Wih1   = (const float*)d_in[17];
    const float* Whh1   = (const float*)d_in[18];
    const float* bih1   = (const float*)d_in[19];
    const float* bhh1   = (const float*)d_in[20];
    const float* Whr1   = (const float*)d_in[21];

    int B = in_sizes[0];            // measurement is (B,1)
    int nblocks = B / BT;

    cudaFuncSetAttribute(fused_kernel,
                         cudaFuncAttributeMaxDynamicSharedMemorySize,
                         SMEM_BYTES);

    prep_kernel<<<128, 256>>>(Wihc, Whhc, bihc, bhhc, Wp,
                              Wih0, Whh0, bih0, bhh0, Whr0,
                              Wih1, Whh1, bih1, bhh1, Whr1);

    fused_kernel<<<nblocks, NTH, SMEM_BYTES>>>(
        meas, br, bi, rho, h0, c0, bp, (float*)d_out);
}

// round 3
// speedup vs baseline: 2.3819x; 2.3819x over previous
#include <cuda_runtime.h>

// ---------------------------------------------------------------------------
// Fused LSTMMeasurementPredictor — round 3
//   B=131072, H=128, NQ=2, P=32, D_IN=17, T=16
// 512 threads / 64-batch tile. FFMA2 with batch-pair accumulators:
// plain (non-duplicated) smem activations, compact weights (1 LDG.128 = 4
// gate columns), per-k weight dup via mov.b64 on the ALU pipe.
// ---------------------------------------------------------------------------

#define NTH 512
#define BT  64
#define SS  68   // padded row stride (floats) for [K][64] smem buffers

constexpr int OFF_X   = 0;                   // 17  rows : x
constexpr int OFF_HC  = OFF_X  + 17  * SS;   // 128 rows : cell h
constexpr int OFF_CC  = OFF_HC + 128 * SS;   // 128 rows : cell c
constexpr int OFF_H0  = OFF_CC + 128 * SS;   // 32  rows : lstm0 proj h
constexpr int OFF_C0  = OFF_H0 + 32  * SS;   // 128 rows : lstm0 c
constexpr int OFF_H1  = OFF_C0 + 128 * SS;   // 32  rows : lstm1 proj h
constexpr int OFF_C1  = OFF_H1 + 32  * SS;   // 128 rows : lstm1 c
constexpr int OFF_SP  = OFF_C1 + 128 * SS;   // 128 rows : s staging
constexpr int OFF_RHO = OFF_SP + 128 * SS;   // 64*33    : rho
constexpr int OFF_V   = OFF_RHO + 64 * 33;   // 8 rows   : projector v
constexpr int SMEM_FLOATS = OFF_V + 8 * SS;
constexpr int SMEM_BYTES  = SMEM_FLOATS * 4; // ~202 KB

// compact packed weights: W[k][512], column jp = u*4 + gate (i,f,g,o)
__device__ __align__(16) float g_Wc[145 * 512];
__device__ __align__(16) float g_bc[512];
__device__ __align__(16) float g_W0[49 * 512];
__device__ __align__(16) float g_b0[512];
__device__ __align__(16) float g_W1[64 * 512];
__device__ __align__(16) float g_b1[512];
__device__ __align__(16) float g_Whr0T[128 * 32];
__device__ __align__(16) float g_Whr1T[128 * 32];
__device__ __align__(16) float g_WpT[128 * 8];

__global__ void prep_kernel(
    const float* __restrict__ Wihc, const float* __restrict__ Whhc,
    const float* __restrict__ bihc, const float* __restrict__ bhhc,
    const float* __restrict__ Wp,
    const float* __restrict__ Wih0, const float* __restrict__ Whh0,
    const float* __restrict__ bih0, const float* __restrict__ bhh0,
    const float* __restrict__ Whr0,
    const float* __restrict__ Wih1, const float* __restrict__ Whh1,
    const float* __restrict__ bih1, const float* __restrict__ bhh1,
    const float* __restrict__ Whr1)
{
    int i0 = blockIdx.x * blockDim.x + threadIdx.x;
    int stride = gridDim.x * blockDim.x;

    for (int i = i0; i < 145 * 512; i += stride) {
        int k = i >> 9, jp = i & 511;
        int u = jp >> 2, g = jp & 3, j = g * 128 + u;
        g_Wc[i] = (k < 17) ? Wihc[j * 17 + k] : Whhc[j * 128 + (k - 17)];
    }
    for (int i = i0; i < 49 * 512; i += stride) {
        int k = i >> 9, jp = i & 511;
        int u = jp >> 2, g = jp & 3, j = g * 128 + u;
        g_W0[i] = (k < 17) ? Wih0[j * 17 + k] : Whh0[j * 32 + (k - 17)];
    }
    for (int i = i0; i < 64 * 512; i += stride) {
        int k = i >> 9, jp = i & 511;
        int u = jp >> 2, g = jp & 3, j = g * 128 + u;
        g_W1[i] = (k < 32) ? Wih1[j * 32 + k] : Whh1[j * 32 + (k - 32)];
    }
    for (int i = i0; i < 512; i += stride) {
        int u = i >> 2, g = i & 3, j = g * 128 + u;
        g_bc[i] = bihc[j] + bhhc[j];
        g_b0[i] = bih0[j] + bhh0[j];
        g_b1[i] = bih1[j] + bhh1[j];
    }
    for (int i = i0; i < 128 * 32; i += stride) {
        int k = i >> 5, n = i & 31;
        g_Whr0T[i] = Whr0[n * 128 + k];
        g_Whr1T[i] = Whr1[n * 128 + k];
    }
    for (int i = i0; i < 128 * 8; i += stride) {
        int k = i >> 3, n = i & 7;
        g_WpT[i] = Wp[n * 128 + k];
    }
}

// ---------------------------------------------------------------------------
typedef unsigned long long ull;

__device__ __forceinline__ void fma2(ull& acc, ull a, ull b) {
    asm("fma.rn.f32x2 %0, %1, %2, %0;" : "+l"(acc) : "l"(a), "l"(b));
}
__device__ __forceinline__ ull dup2(float x) {
    ull r;
    asm("mov.b64 %0, {%1, %1};" : "=l"(r) : "f"(x));
    return r;
}
__device__ __forceinline__ void unpk(ull v, float& lo, float& hi) {
    asm("mov.b64 {%0, %1}, %2;" : "=f"(lo), "=f"(hi) : "l"(v));
}

__device__ __forceinline__ float fsig(float x) {
    return __fdividef(1.0f, 1.0f + __expf(-x));
}
__device__ __forceinline__ float ftanh(float x) {
    return __fdividef(2.0f, 1.0f + __expf(-2.0f * x)) - 1.0f;
}

// LSTM step: G[64,512] = [A(KA); B(KB)] @ W + bias, then gate update.
// Thread: unit u = tid&127 (cols 4u..4u+3), batches b0 = (tid>>7)*16 .. +15.
// acc[col][pair] with pair = (batch 2p, 2p+1). Internal __syncthreads between
// the read phase (k-loop) and the write phase (epilogue) makes it safe to
// write outputs into buffers the k-loop read (incl. shOut == shB aliasing).
template <int KA, int KB>
__device__ __forceinline__ void lstm_step(
    const float* __restrict__ W, const float* __restrict__ bias,
    const float* shA, const float* shB, float* shC, float* shOut,
    int u, int b0)
{
    ull acc[4][8];
    {
        float4 bs = *(const float4*)(bias + 4 * u);
        ull d0 = dup2(bs.x), d1 = dup2(bs.y), d2 = dup2(bs.z), d3 = dup2(bs.w);
#pragma unroll
        for (int p = 0; p < 8; ++p) {
            acc[0][p] = d0; acc[1][p] = d1; acc[2][p] = d2; acc[3][p] = d3;
        }
    }
    const float* Wb_ = W + 4 * u;
#pragma unroll 4
    for (int k = 0; k < KA; ++k) {
        float4 w = __ldg((const float4*)(Wb_ + k * 512));
        ull w0 = dup2(w.x), w1 = dup2(w.y), w2 = dup2(w.z), w3 = dup2(w.w);
        const float* ap = shA + k * SS + b0;
        ulonglong2 aA = *(const ulonglong2*)(ap);
        ulonglong2 aB = *(const ulonglong2*)(ap + 4);
        ulonglong2 aC = *(const ulonglong2*)(ap + 8);
        ulonglong2 aD = *(const ulonglong2*)(ap + 12);
        ull av[8] = {aA.x, aA.y, aB.x, aB.y, aC.x, aC.y, aD.x, aD.y};
#pragma unroll
        for (int p = 0; p < 8; ++p) {
            fma2(acc[0][p], w0, av[p]);
            fma2(acc[1][p], w1, av[p]);
            fma2(acc[2][p], w2, av[p]);
            fma2(acc[3][p], w3, av[p]);
        }
    }
    const float* Wb2 = W + KA * 512 + 4 * u;
#pragma unroll 4
    for (int k = 0; k < KB; ++k) {
        float4 w = __ldg((const float4*)(Wb2 + k * 512));
        ull w0 = dup2(w.x), w1 = dup2(w.y), w2 = dup2(w.z), w3 = dup2(w.w);
        const float* ap = shB + k * SS + b0;
        ulonglong2 aA = *(const ulonglong2*)(ap);
        ulonglong2 aB = *(const ulonglong2*)(ap + 4);
        ulonglong2 aC = *(const ulonglong2*)(ap + 8);
        ulonglong2 aD = *(const ulonglong2*)(ap + 12);
        ull av[8] = {aA.x, aA.y, aB.x, aB.y, aC.x, aC.y, aD.x, aD.y};
#pragma unroll
        for (int p = 0; p < 8; ++p) {
            fma2(acc[0][p], w0, av[p]);
            fma2(acc[1][p], w1, av[p]);
            fma2(acc[2][p], w2, av[p]);
            fma2(acc[3][p], w3, av[p]);
        }
    }

    __syncthreads();   // all reads of shA/shB/shOut done chip... CTA-wide

    // epilogue: gates -> c update -> s
#pragma unroll
    for (int q = 0; q < 4; ++q) {
        int bq = b0 + 4 * q;
        float gi[4], gf[4], gg[4], go[4];
        unpk(acc[0][2 * q], gi[0], gi[1]); unpk(acc[0][2 * q + 1], gi[2], gi[3]);
        unpk(acc[1][2 * q], gf[0], gf[1]); unpk(acc[1][2 * q + 1], gf[2], gf[3]);
        unpk(acc[2][2 * q], gg[0], gg[1]); unpk(acc[2][2 * q + 1], gg[2], gg[3]);
        unpk(acc[3][2 * q], go[0], go[1]); unpk(acc[3][2 * q + 1], go[2], go[3]);
        float4 cv = *(const float4*)(shC + u * SS + bq);
        float cb[4] = {cv.x, cv.y, cv.z, cv.w};
        float sb[4];
#pragma unroll
        for (int j = 0; j < 4; ++j) {
            float cn = fsig(gf[j]) * cb[j] + fsig(gi[j]) * ftanh(gg[j]);
            cb[j] = cn;
            sb[j] = fsig(go[j]) * ftanh(cn);
        }
        *(float4*)(shC + u * SS + bq)   = make_float4(cb[0], cb[1], cb[2], cb[3]);
        *(float4*)(shOut + u * SS + bq) = make_float4(sb[0], sb[1], sb[2], sb[3]);
    }
}

// hp[64,32] = s[64,128] @ WhrT[128,32]. Thread: cols n4..n4+3, one batch.
__device__ __forceinline__ void proj_gemm(
    const float* __restrict__ WT, const float* shS, float* shHdst,
    float* outp, int tid)
{
    const int n4 = (tid & 7) * 4;
    const int b  = tid >> 3;
    ull acc0 = 0ull, acc1 = 0ull;
#pragma unroll 8
    for (int k = 0; k < 128; ++k) {
        ulonglong2 wp = __ldg((const ulonglong2*)(WT + k * 32 + n4));
        ull sd = dup2(shS[k * SS + b]);
        fma2(acc0, wp.x, sd);
        fma2(acc1, wp.y, sd);
    }
    float a0, a1, a2, a3;
    unpk(acc0, a0, a1);
    unpk(acc1, a2, a3);
    shHdst[(n4 + 0) * SS + b] = a0;
    shHdst[(n4 + 1) * SS + b] = a1;
    shHdst[(n4 + 2) * SS + b] = a2;
    shHdst[(n4 + 3) * SS + b] = a3;
    if (outp) {
        *(float4*)(outp + (size_t)b * 512 + n4) = make_float4(a0, a1, a2, a3);
    }
}

// quantum measurement physics for one batch element b (0..63)
__device__ __forceinline__ void physics(const float* shV, const float* shRHO,
                                        float* shX, int b)
{
    float Mr[2][2][2], Mi[2][2][2];
#pragma unroll
    for (int q = 0; q < 2; ++q) {
        float ar = shV[(q * 4 + 0) * SS + b];
        float ai = shV[(q * 4 + 1) * SS + b];
        float br = shV[(q * 4 + 2) * SS + b];
        float bi = shV[(q * 4 + 3) * SS + b];
        float n00 = ar * ar + ai * ai;
        float n11 = br * br + bi * bi;
        float inv = 1.0f / (n00 + n11);
        float pr = (ar * br + ai * bi) * inv;
        float pi = (ai * br - ar * bi) * inv;
        Mr[q][0][0] = n00 * inv; Mi[q][0][0] = 0.f;
        Mr[q][0][1] = pr;        Mi[q][0][1] = pi;
        Mr[q][1][0] = pr;        Mi[q][1][0] = -pi;
        Mr[q][1][1] = n11 * inv; Mi[q][1][1] = 0.f;
    }
    const float* rp = shRHO + b * 33;
    float m = 0.f;
#pragma unroll
    for (int a = 0; a < 2; ++a)
#pragma unroll
        for (int c = 0; c < 2; ++c)
#pragma unroll
            for (int b2 = 0; b2 < 2; ++b2)
#pragma unroll
                for (int d = 0; d < 2; ++d) {
                    float tr_ = Mr[0][a][c] * Mr[1][b2][d] - Mi[0][a][c] * Mi[1][b2][d];
                    float ti_ = Mr[0][a][c] * Mi[1][b2][d] + Mi[0][a][c] * Mr[1][b2][d];
                    int row = c * 2 + d, col = a * 2 + b2;
                    float rr = rp[row * 4 + col];
                    float ri = rp[16 + row * 4 + col];
                    m += tr_ * rr - ti_ * ri;
                }
    shX[0 * SS + b] = m;
#pragma unroll
    for (int q = 0; q < 2; ++q)
#pragma unroll
        for (int i = 0; i < 2; ++i)
#pragma unroll
            for (int j = 0; j < 2; ++j) {
                int base = 1 + 8 * q + 4 * i + 2 * j;
                shX[base * SS + b]       = Mr[q][i][j];
                shX[(base + 1) * SS + b] = Mi[q][i][j];
            }
}

__global__ void __launch_bounds__(NTH, 1) fused_kernel(
    const float* __restrict__ meas, const float* __restrict__ basis_r,
    const float* __restrict__ basis_i, const float* __restrict__ rho,
    const float* __restrict__ h0in, const float* __restrict__ c0in,
    const float* __restrict__ bp, float* __restrict__ out)
{
    extern __shared__ float sm[];
    float* shX   = sm + OFF_X;
    float* shHC  = sm + OFF_HC;
    float* shCC  = sm + OFF_CC;
    float* shH0  = sm + OFF_H0;
    float* shC0  = sm + OFF_C0;
    float* shH1  = sm + OFF_H1;
    float* shC1  = sm + OFF_C1;
    float* shSP  = sm + OFF_SP;
    float* shRHO = sm + OFF_RHO;
    float* shV   = sm + OFF_V;

    const int tid = threadIdx.x;
    const int b0g = blockIdx.x * BT;

    // ---- init loads ----
    for (int i = tid; i < BT; i += NTH)
        shX[0 * SS + i] = meas[b0g + i];
    for (int i = tid; i < BT * 8; i += NTH) {
        int b = i >> 3, e = i & 7;
        shX[(1 + 2 * e) * SS + b] = basis_r[(size_t)(b0g + b) * 8 + e];
        shX[(2 + 2 * e) * SS + b] = basis_i[(size_t)(b0g + b) * 8 + e];
    }
    for (int i = tid; i < BT * 32; i += NTH) {
        int b = i >> 5, e = i & 31;
        shRHO[b * 33 + e] = rho[(size_t)(b0g + b) * 32 + e];
    }
    for (int i = tid; i < BT * 128; i += NTH) {
        int b = i >> 7, u = i & 127;
        shHC[u * SS + b] = h0in[(size_t)(b0g + b) * 128 + u];
        shCC[u * SS + b] = c0in[(size_t)(b0g + b) * 128 + u];
    }
    // zero H0, C0, H1, C1 (320 contiguous rows)
    for (int i = tid; i < 320 * SS; i += NTH)
        sm[OFF_H0 + i] = 0.f;
    __syncthreads();

    const int u  = tid & 127;
    const int b0 = (tid >> 7) * 16;

    for (int t = 0; t < 16; ++t) {
        // LSTM0: [x(17); hp0(32)] -> s in SP, c in C0
        lstm_step<17, 32>(g_W0, g_b0, shX, shH0, shC0, shSP, u, b0);
        __syncthreads();
        proj_gemm(g_Whr0T, shSP, shH0, nullptr, tid);
        __syncthreads();
        // LSTM1: [hp0(32); hp1(32)]
        lstm_step<32, 32>(g_W1, g_b1, shH0, shH1, shC1, shSP, u, b0);
        __syncthreads();
        proj_gemm(g_Whr1T, shSP, shH1,
                  out + (size_t)b0g * 512 + (size_t)t * 32, tid);
        __syncthreads();

        if (t < 15) {
            // cell: [x(17); h(128)] -> h_new written directly into HC
            lstm_step<17, 128>(g_Wc, g_bc, shX, shHC, shCC, shHC, u, b0);
            __syncthreads();
            // projector v[8,64] = h_new @ WpT + bp
            {
                int nn = tid >> 6, bb = tid & 63;
                float a = __ldg(&bp[nn]);
#pragma unroll 8
                for (int k = 0; k < 128; ++k)
                    a += shHC[k * SS + bb] * __ldg(&g_WpT[k * 8 + nn]);
                shV[nn * SS + bb] = a;
            }
            __syncthreads();
            if (tid < BT) physics(shV, shRHO, shX, tid);
            __syncthreads();
        }
    }
}

extern "C" void kernel_launch(void* const* d_in, const int* in_sizes, int n_in,
                              void* d_out, int out_size)
{
    const float* meas   = (const float*)d_in[0];
    const float* br     = (const float*)d_in[1];
    const float* bi     = (const float*)d_in[2];
    const float* rho    = (const float*)d_in[3];
    const float* h0     = (const float*)d_in[4];
    const float* c0     = (const float*)d_in[5];
    const float* Wihc   = (const float*)d_in[6];
    const float* Whhc   = (const float*)d_in[7];
    const float* bihc   = (const float*)d_in[8];
    const float* bhhc   = (const float*)d_in[9];
    const float* Wp     = (const float*)d_in[10];
    const float* bp     = (const float*)d_in[11];
    const float* Wih0   = (const float*)d_in[12];
    const float* Whh0   = (const float*)d_in[13];
    const float* bih0   = (const float*)d_in[14];
    const float* bhh0   = (const float*)d_in[15];
    const float* Whr0   = (const float*)d_in[16];
    const float* Wih1   = (const float*)d_in[17];
    const float* Whh1   = (const float*)d_in[18];
    const float* bih1   = (const float*)d_in[19];
    const float* bhh1   = (const float*)d_in[20];
    const float* Whr1   = (const float*)d_in[21];

    int B = in_sizes[0];
    int nblocks = B / BT;

    cudaFuncSetAttribute(fused_kernel,
                         cudaFuncAttributeMaxDynamicSharedMemorySize,
                         SMEM_BYTES);

    prep_kernel<<<128, 256>>>(Wihc, Whhc, bihc, bhhc, Wp,
                              Wih0, Whh0, bih0, bhh0, Whr0,
                              Wih1, Whh1, bih1, bhh1, Whr1);

    fused_kernel<<<nblocks, NTH, SMEM_BYTES>>>(
        meas, br, bi, rho, h0, c0, bp, (float*)d_out);
}

// round 4
// speedup vs baseline: 2.5940x; 1.0891x over previous
#include <cuda_runtime.h>

// ---------------------------------------------------------------------------
// Fused LSTMMeasurementPredictor — round 4
//   B=131072, H=128, NQ=2, P=32, D_IN=17, T=16
// 512 threads / 64-batch tile. FFMA2 batch-pair accumulators.
// New vs R3: fused single k-loop with distance-2 weight prefetch, reduced
// register footprint (chunked activation loads), HC ping-pong (no staging
// copy, no internal barrier), 7 barriers/step instead of 11.
// ---------------------------------------------------------------------------

#define NTH 512
#define BT  64
#define SS  68   // padded row stride (floats) for [K][64] smem buffers

constexpr int OFF_X   = 0;                   // 17  rows : x
constexpr int OFF_HCA = OFF_X   + 17  * SS;  // 128 rows : cell h (ping)
constexpr int OFF_HCB = OFF_HCA + 128 * SS;  // 128 rows : cell h (pong) / s staging
constexpr int OFF_CC  = OFF_HCB + 128 * SS;  // 128 rows : cell c
constexpr int OFF_H0  = OFF_CC  + 128 * SS;  // 32  rows : lstm0 proj h
constexpr int OFF_C0  = OFF_H0  + 32  * SS;  // 128 rows : lstm0 c
constexpr int OFF_H1  = OFF_C0  + 128 * SS;  // 32  rows : lstm1 proj h
constexpr int OFF_C1  = OFF_H1  + 32  * SS;  // 128 rows : lstm1 c
constexpr int OFF_RHO = OFF_C1  + 128 * SS;  // 64*33    : rho
constexpr int OFF_V   = OFF_RHO + 64 * 33;   // 8 rows   : projector v
constexpr int SMEM_FLOATS = OFF_V + 8 * SS;
constexpr int SMEM_BYTES  = SMEM_FLOATS * 4; // ~202 KB

// compact packed weights: W[k][512], column jp = u*4 + gate (i,f,g,o).
// +1024 floats pad so the distance-2 prefetch can overshoot by 2 rows.
__device__ __align__(16) float g_Wc[145 * 512 + 1024];
__device__ __align__(16) float g_bc[512];
__device__ __align__(16) float g_W0[49 * 512 + 1024];
__device__ __align__(16) float g_b0[512];
__device__ __align__(16) float g_W1[64 * 512 + 1024];
__device__ __align__(16) float g_b1[512];
__device__ __align__(16) float g_Whr0T[128 * 32];
__device__ __align__(16) float g_Whr1T[128 * 32];
__device__ __align__(16) float g_WpT[128 * 8];

__global__ void prep_kernel(
    const float* __restrict__ Wihc, const float* __restrict__ Whhc,
    const float* __restrict__ bihc, const float* __restrict__ bhhc,
    const float* __restrict__ Wp,
    const float* __restrict__ Wih0, const float* __restrict__ Whh0,
    const float* __restrict__ bih0, const float* __restrict__ bhh0,
    const float* __restrict__ Whr0,
    const float* __restrict__ Wih1, const float* __restrict__ Whh1,
    const float* __restrict__ bih1, const float* __restrict__ bhh1,
    const float* __restrict__ Whr1)
{
    int i0 = blockIdx.x * blockDim.x + threadIdx.x;
    int stride = gridDim.x * blockDim.x;

    for (int i = i0; i < 145 * 512; i += stride) {
        int k = i >> 9, jp = i & 511;
        int u = jp >> 2, g = jp & 3, j = g * 128 + u;
        g_Wc[i] = (k < 17) ? Wihc[j * 17 + k] : Whhc[j * 128 + (k - 17)];
    }
    for (int i = i0; i < 49 * 512; i += stride) {
        int k = i >> 9, jp = i & 511;
        int u = jp >> 2, g = jp & 3, j = g * 128 + u;
        g_W0[i] = (k < 17) ? Wih0[j * 17 + k] : Whh0[j * 32 + (k - 17)];
    }
    for (int i = i0; i < 64 * 512; i += stride) {
        int k = i >> 9, jp = i & 511;
        int u = jp >> 2, g = jp & 3, j = g * 128 + u;
        g_W1[i] = (k < 32) ? Wih1[j * 32 + k] : Whh1[j * 32 + (k - 32)];
    }
    // zero the prefetch-overshoot pads (avoid reading uninitialized global)
    for (int i = i0; i < 1024; i += stride) {
        g_Wc[145 * 512 + i] = 0.f;
        g_W0[49 * 512 + i] = 0.f;
        g_W1[64 * 512 + i] = 0.f;
    }
    for (int i = i0; i < 512; i += stride) {
        int u = i >> 2, g = i & 3, j = g * 128 + u;
        g_bc[i] = bihc[j] + bhhc[j];
        g_b0[i] = bih0[j] + bhh0[j];
        g_b1[i] = bih1[j] + bhh1[j];
    }
    for (int i = i0; i < 128 * 32; i += stride) {
        int k = i >> 5, n = i & 31;
        g_Whr0T[i] = Whr0[n * 128 + k];
        g_Whr1T[i] = Whr1[n * 128 + k];
    }
    for (int i = i0; i < 128 * 8; i += stride) {
        int k = i >> 3, n = i & 7;
        g_WpT[i] = Wp[n * 128 + k];
    }
}

// ---------------------------------------------------------------------------
typedef unsigned long long ull;

__device__ __forceinline__ void fma2(ull& acc, ull a, ull b) {
    asm("fma.rn.f32x2 %0, %1, %2, %0;" : "+l"(acc) : "l"(a), "l"(b));
}
__device__ __forceinline__ ull dup2(float x) {
    ull r;
    asm("mov.b64 %0, {%1, %1};" : "=l"(r) : "f"(x));
    return r;
}
__device__ __forceinline__ void unpk(ull v, float& lo, float& hi) {
    asm("mov.b64 {%0, %1}, %2;" : "=f"(lo), "=f"(hi) : "l"(v));
}

__device__ __forceinline__ float fsig(float x) {
    return __fdividef(1.0f, 1.0f + __expf(-x));
}
__device__ __forceinline__ float ftanh(float x) {
    return __fdividef(2.0f, 1.0f + __expf(-2.0f * x)) - 1.0f;
}

// LSTM step: G[64,512] = [A(KA); B(KB)] @ W + bias, then gate update.
// Thread: unit u = tid&127 (cols 4u..4u+3), batches b0 = (tid>>7)*16 .. +15.
// Single fused k-loop (weights contiguous), distance-2 weight prefetch.
// NO internal barrier: caller guarantees {shC, shOut} are disjoint from
// {shA, shB} (per-(u,b) elements of shC/shOut owned by exactly one thread).
template <int KA, int KB>
__device__ __forceinline__ void lstm_step(
    const float* __restrict__ W, const float* __restrict__ bias,
    const float* shA, const float* shB, float* shC, float* shOut,
    int u, int b0)
{
    constexpr int K = KA + KB;
    ull acc[4][8];
    {
        float4 bs = *(const float4*)(bias + 4 * u);
        ull d0 = dup2(bs.x), d1 = dup2(bs.y), d2 = dup2(bs.z), d3 = dup2(bs.w);
#pragma unroll
        for (int p = 0; p < 8; ++p) {
            acc[0][p] = d0; acc[1][p] = d1; acc[2][p] = d2; acc[3][p] = d3;
        }
    }
    const float* Wu    = W + 4 * u;
    const float* baseA = shA + b0;
    const float* baseB = shB + b0 - KA * SS;   // so that base + k*SS is valid

    float4 w0 = __ldg((const float4*)(Wu));
    float4 w1 = __ldg((const float4*)(Wu + 512));
#pragma unroll 4
    for (int k = 0; k < K; ++k) {
        float4 wn = __ldg((const float4*)(Wu + (k + 2) * 512));   // pad-safe
        const float* ap = (k < KA ? baseA : baseB) + k * SS;
        ull wd0 = dup2(w0.x), wd1 = dup2(w0.y), wd2 = dup2(w0.z), wd3 = dup2(w0.w);
#pragma unroll
        for (int c = 0; c < 4; ++c) {
            ulonglong2 a = *(const ulonglong2*)(ap + 4 * c);
            fma2(acc[0][2 * c], wd0, a.x); fma2(acc[0][2 * c + 1], wd0, a.y);
            fma2(acc[1][2 * c], wd1, a.x); fma2(acc[1][2 * c + 1], wd1, a.y);
            fma2(acc[2][2 * c], wd2, a.x); fma2(acc[2][2 * c + 1], wd2, a.y);
            fma2(acc[3][2 * c], wd3, a.x); fma2(acc[3][2 * c + 1], wd3, a.y);
        }
        w0 = w1; w1 = wn;
    }

    // epilogue: gates -> c update -> s
#pragma unroll
    for (int q = 0; q < 4; ++q) {
        int bq = b0 + 4 * q;
        float gi[4], gf[4], gg[4], go[4];
        unpk(acc[0][2 * q], gi[0], gi[1]); unpk(acc[0][2 * q + 1], gi[2], gi[3]);
        unpk(acc[1][2 * q], gf[0], gf[1]); unpk(acc[1][2 * q + 1], gf[2], gf[3]);
        unpk(acc[2][2 * q], gg[0], gg[1]); unpk(acc[2][2 * q + 1], gg[2], gg[3]);
        unpk(acc[3][2 * q], go[0], go[1]); unpk(acc[3][2 * q + 1], go[2], go[3]);
        float4 cv = *(const float4*)(shC + u * SS + bq);
        float cb[4] = {cv.x, cv.y, cv.z, cv.w};
        float sb[4];
#pragma unroll
        for (int j = 0; j < 4; ++j) {
            float cn = fsig(gf[j]) * cb[j] + fsig(gi[j]) * ftanh(gg[j]);
            cb[j] = cn;
            sb[j] = fsig(go[j]) * ftanh(cn);
        }
        *(float4*)(shC + u * SS + bq)   = make_float4(cb[0], cb[1], cb[2], cb[3]);
        *(float4*)(shOut + u * SS + bq) = make_float4(sb[0], sb[1], sb[2], sb[3]);
    }
}

// hp[64,32] = s[64,128] @ WhrT[128,32]. Thread: cols n4..n4+3, one batch.
__device__ __forceinline__ void proj_gemm(
    const float* __restrict__ WT, const float* shS, float* shHdst,
    float* outp, int tid)
{
    const int n4 = (tid & 7) * 4;
    const int b  = tid >> 3;
    ull acc0 = 0ull, acc1 = 0ull;
#pragma unroll 8
    for (int k = 0; k < 128; ++k) {
        ulonglong2 wp = __ldg((const ulonglong2*)(WT + k * 32 + n4));
        ull sd = dup2(shS[k * SS + b]);
        fma2(acc0, wp.x, sd);
        fma2(acc1, wp.y, sd);
    }
    float a0, a1, a2, a3;
    unpk(acc0, a0, a1);
    unpk(acc1, a2, a3);
    shHdst[(n4 + 0) * SS + b] = a0;
    shHdst[(n4 + 1) * SS + b] = a1;
    shHdst[(n4 + 2) * SS + b] = a2;
    shHdst[(n4 + 3) * SS + b] = a3;
    if (outp) {
        *(float4*)(outp + (size_t)b * 512 + n4) = make_float4(a0, a1, a2, a3);
    }
}

// quantum measurement physics for one batch element b (0..63)
__device__ __forceinline__ void physics(const float* shV, const float* shRHO,
                                        float* shX, int b)
{
    float Mr[2][2][2], Mi[2][2][2];
#pragma unroll
    for (int q = 0; q < 2; ++q) {
        float ar = shV[(q * 4 + 0) * SS + b];
        float ai = shV[(q * 4 + 1) * SS + b];
        float br = shV[(q * 4 + 2) * SS + b];
        float bi = shV[(q * 4 + 3) * SS + b];
        float n00 = ar * ar + ai * ai;
        float n11 = br * br + bi * bi;
        float inv = 1.0f / (n00 + n11);
        float pr = (ar * br + ai * bi) * inv;
        float pi = (ai * br - ar * bi) * inv;
        Mr[q][0][0] = n00 * inv; Mi[q][0][0] = 0.f;
        Mr[q][0][1] = pr;        Mi[q][0][1] = pi;
        Mr[q][1][0] = pr;        Mi[q][1][0] = -pi;
        Mr[q][1][1] = n11 * inv; Mi[q][1][1] = 0.f;
    }
    const float* rp = shRHO + b * 33;
    float m = 0.f;
#pragma unroll
    for (int a = 0; a < 2; ++a)
#pragma unroll
        for (int c = 0; c < 2; ++c)
#pragma unroll
            for (int b2 = 0; b2 < 2; ++b2)
#pragma unroll
                for (int d = 0; d < 2; ++d) {
                    float tr_ = Mr[0][a][c] * Mr[1][b2][d] - Mi[0][a][c] * Mi[1][b2][d];
                    float ti_ = Mr[0][a][c] * Mi[1][b2][d] + Mi[0][a][c] * Mr[1][b2][d];
                    int row = c * 2 + d, col = a * 2 + b2;
                    float rr = rp[row * 4 + col];
                    float ri = rp[16 + row * 4 + col];
                    m += tr_ * rr - ti_ * ri;
                }
    shX[0 * SS + b] = m;
#pragma unroll
    for (int q = 0; q < 2; ++q)
#pragma unroll
        for (int i = 0; i < 2; ++i)
#pragma unroll
            for (int j = 0; j < 2; ++j) {
                int base = 1 + 8 * q + 4 * i + 2 * j;
                shX[base * SS + b]       = Mr[q][i][j];
                shX[(base + 1) * SS + b] = Mi[q][i][j];
            }
}

__global__ void __launch_bounds__(NTH, 1) fused_kernel(
    const float* __restrict__ meas, const float* __restrict__ basis_r,
    const float* __restrict__ basis_i, const float* __restrict__ rho,
    const float* __restrict__ h0in, const float* __restrict__ c0in,
    const float* __restrict__ bp, float* __restrict__ out)
{
    extern __shared__ float sm[];
    float* shX   = sm + OFF_X;
    float* shCC  = sm + OFF_CC;
    float* shH0  = sm + OFF_H0;
    float* shC0  = sm + OFF_C0;
    float* shH1  = sm + OFF_H1;
    float* shC1  = sm + OFF_C1;
    float* shRHO = sm + OFF_RHO;
    float* shV   = sm + OFF_V;

    const int tid = threadIdx.x;
    const int b0g = blockIdx.x * BT;

    // ---- init loads ----
    for (int i = tid; i < BT; i += NTH)
        shX[0 * SS + i] = meas[b0g + i];
    for (int i = tid; i < BT * 8; i += NTH) {
        int b = i >> 3, e = i & 7;
        shX[(1 + 2 * e) * SS + b] = basis_r[(size_t)(b0g + b) * 8 + e];
        shX[(2 + 2 * e) * SS + b] = basis_i[(size_t)(b0g + b) * 8 + e];
    }
    for (int i = tid; i < BT * 32; i += NTH) {
        int b = i >> 5, e = i & 31;
        shRHO[b * 33 + e] = rho[(size_t)(b0g + b) * 32 + e];
    }
    for (int i = tid; i < BT * 128; i += NTH) {
        int b = i >> 7, u = i & 127;
        sm[OFF_HCA + u * SS + b] = h0in[(size_t)(b0g + b) * 128 + u];
        shCC[u * SS + b]         = c0in[(size_t)(b0g + b) * 128 + u];
    }
    // zero H0, C0, H1, C1 (320 contiguous rows)
    for (int i = tid; i < 320 * SS; i += NTH)
        sm[OFF_H0 + i] = 0.f;
    __syncthreads();

    const int u  = tid & 127;
    const int b0 = (tid >> 7) * 16;

    float* hcur = sm + OFF_HCA;   // cell h state (valid)
    float* hnxt = sm + OFF_HCB;   // scratch: s staging + next cell h

    for (int t = 0; t < 16; ++t) {
        // LSTM0: reads X,H0,C0; writes s->hnxt, C0
        lstm_step<17, 32>(g_W0, g_b0, shX, shH0, shC0, hnxt, u, b0);
        __syncthreads();
        proj_gemm(g_Whr0T, hnxt, shH0, nullptr, tid);        // reads hnxt -> H0
        __syncthreads();
        // LSTM1: reads H0,H1,C1; writes s->hnxt, C1
        lstm_step<32, 32>(g_W1, g_b1, shH0, shH1, shC1, hnxt, u, b0);
        __syncthreads();
        proj_gemm(g_Whr1T, hnxt, shH1,
                  out + (size_t)b0g * 512 + (size_t)t * 32, tid);
        __syncthreads();

        if (t < 15) {
            // cell: reads X, hcur, CC; writes h_new->hnxt, CC
            lstm_step<17, 128>(g_Wc, g_bc, shX, hcur, shCC, hnxt, u, b0);
            __syncthreads();
            // projector v[8,64] = h_new @ WpT + bp
            {
                int nn = tid >> 6, bb = tid & 63;
                float a = __ldg(&bp[nn]);
#pragma unroll 8
                for (int k = 0; k < 128; ++k)
                    a += hnxt[k * SS + bb] * __ldg(&g_WpT[k * 8 + nn]);
                shV[nn * SS + bb] = a;
            }
            __syncthreads();
            if (tid < BT) physics(shV, shRHO, shX, tid);
            __syncthreads();
            // swap ping-pong: h_new becomes current
            float* tmp = hcur; hcur = hnxt; hnxt = tmp;
        }
    }
}

extern "C" void kernel_launch(void* const* d_in, const int* in_sizes, int n_in,
                              void* d_out, int out_size)
{
    const float* meas   = (const float*)d_in[0];
    const float* br     = (const float*)d_in[1];
    const float* bi     = (const float*)d_in[2];
    const float* rho    = (const float*)d_in[3];
    const float* h0     = (const float*)d_in[4];
    const float* c0     = (const float*)d_in[5];
    const float* Wihc   = (const float*)d_in[6];
    const float* Whhc   = (const float*)d_in[7];
    const float* bihc   = (const float*)d_in[8];
    const float* bhhc   = (const float*)d_in[9];
    const float* Wp     = (const float*)d_in[10];
    const float* bp     = (const float*)d_in[11];
    const float* Wih0   = (const float*)d_in[12];
    const float* Whh0   = (const float*)d_in[13];
    const float* bih0   = (const float*)d_in[14];
    const float* bhh0   = (const float*)d_in[15];
    const float* Whr0   = (const float*)d_in[16];
    const float* Wih1   = (const float*)d_in[17];
    const float* Whh1   = (const float*)d_in[18];
    const float* bih1   = (const float*)d_in[19];
    const float* bhh1   = (const float*)d_in[20];
    const float* Whr1   = (const float*)d_in[21];

    int B = in_sizes[0];
    int nblocks = B / BT;

    cudaFuncSetAttribute(fused_kernel,
                         cudaFuncAttributeMaxDynamicSharedMemorySize,
                         SMEM_BYTES);

    prep_kernel<<<128, 256>>>(Wihc, Whhc, bihc, bhhc, Wp,
                              Wih0, Whh0, bih0, bhh0, Whr0,
                              Wih1, Whh1, bih1, bhh1, Whr1);

    fused_kernel<<<nblocks, NTH, SMEM_BYTES>>>(
        meas, br, bi, rho, h0, c0, bp, (float*)d_out);
}